// round 8
// baseline (speedup 1.0000x reference)
#include <cuda_runtime.h>
#include <cuda_bf16.h>
#include <mma.h>
#include <cstdint>

using namespace nvcuda;

#define N_NODES   100000
#define N_EDGES   1600000
#define D_FEAT    128
#define HIDDEN    128
#define N_CLASSES 10
#define NUM_GRAPHS 64
#define N_PAD     100096   // 391 * 256

typedef __nv_bfloat16 bf16;
typedef __nv_bfloat162 bf162;

// ---------------- scratch (no allocs allowed) ----------------
__device__ bf16 g_xhi[(size_t)N_PAD * 128];
__device__ bf16 g_xlo[(size_t)N_PAD * 128];
__device__ bf16 g_ahi[(size_t)N_PAD * 128];
__device__ bf16 g_alo[(size_t)N_PAD * 128];
__device__ bf16 g_h0hi[(size_t)N_PAD * 128];
__device__ bf16 g_h0lo[(size_t)N_PAD * 128];
__device__ bf16 g_h1hi[(size_t)N_PAD * 128];
__device__ bf16 g_h1lo[(size_t)N_PAD * 128];
__device__ bf16 g_whi[3 * 128 * 256];
__device__ bf16 g_wlo[3 * 128 * 256];
__device__ float g_pooled[NUM_GRAPHS * HIDDEN];
__device__ int   g_deg [N_NODES];
__device__ int   g_off [N_NODES + 1];
__device__ int   g_cur [N_NODES];
__device__ int   g_srcs[N_EDGES];

// ---------------- helpers ----------------
__device__ __forceinline__ uint32_t smem_u32(const void* p) {
    uint32_t a;
    asm("{ .reg .u64 t; cvta.to.shared.u64 t, %1; cvt.u32.u64 %0, t; }" : "=r"(a) : "l"(p));
    return a;
}
__device__ __forceinline__ void cp16(uint32_t dst, const void* src) {
    asm volatile("cp.async.cg.shared.global [%0], [%1], 16;" :: "r"(dst), "l"(src));
}
#define CP_COMMIT() asm volatile("cp.async.commit_group;" ::: "memory")
#define CP_WAIT1()  asm volatile("cp.async.wait_group 1;" ::: "memory")
#define CP_WAIT0()  asm volatile("cp.async.wait_group 0;" ::: "memory")

__device__ __forceinline__ float4 rec4(uint2 hi, uint2 lo) {
    bf162 h0 = *reinterpret_cast<bf162*>(&hi.x);
    bf162 h1 = *reinterpret_cast<bf162*>(&hi.y);
    bf162 l0 = *reinterpret_cast<bf162*>(&lo.x);
    bf162 l1 = *reinterpret_cast<bf162*>(&lo.y);
    float4 v;
    v.x = __bfloat162float(h0.x) + __bfloat162float(l0.x);
    v.y = __bfloat162float(h0.y) + __bfloat162float(l0.y);
    v.z = __bfloat162float(h1.x) + __bfloat162float(l1.x);
    v.w = __bfloat162float(h1.y) + __bfloat162float(l1.y);
    return v;
}
// split float4 -> hi/lo uint2 pair
__device__ __forceinline__ void split4(float4 v, uint2& hi, uint2& lo) {
    bf162 h0, h1, l0, l1;
    h0.x = __float2bfloat16(v.x); h0.y = __float2bfloat16(v.y);
    h1.x = __float2bfloat16(v.z); h1.y = __float2bfloat16(v.w);
    l0.x = __float2bfloat16(v.x - __bfloat162float(h0.x));
    l0.y = __float2bfloat16(v.y - __bfloat162float(h0.y));
    l1.x = __float2bfloat16(v.z - __bfloat162float(h1.x));
    l1.y = __float2bfloat16(v.w - __bfloat162float(h1.y));
    hi.x = *reinterpret_cast<uint32_t*>(&h0); hi.y = *reinterpret_cast<uint32_t*>(&h1);
    lo.x = *reinterpret_cast<uint32_t*>(&l0); lo.y = *reinterpret_cast<uint32_t*>(&l1);
}

// ---------------- conversions ----------------
__global__ void __launch_bounds__(256) cvt_x_kernel(
    const float* __restrict__ x, bf16* __restrict__ xhi, bf16* __restrict__ xlo)
{
    int t = blockIdx.x * blockDim.x + threadIdx.x;
    if (t >= N_NODES * 32) return;
    float4 v = __ldg(reinterpret_cast<const float4*>(x) + t);
    uint2 hi, lo;
    split4(v, hi, lo);
    *reinterpret_cast<uint2*>(xhi + (size_t)t * 4) = hi;
    *reinterpret_cast<uint2*>(xlo + (size_t)t * 4) = lo;
}

__global__ void __launch_bounds__(256) cvt_w_kernel(
    const float* __restrict__ W1l, const float* __restrict__ W1r,
    const float* __restrict__ W2l, const float* __restrict__ W2r,
    const float* __restrict__ W3l, const float* __restrict__ W3r,
    bf16* __restrict__ whi, bf16* __restrict__ wlo)
{
    int id = blockIdx.x * blockDim.x + threadIdx.x;   // 3*128*256
    if (id >= 3 * 128 * 256) return;
    int l = id >> 15;
    int r = (id >> 8) & 127;
    int k = id & 255;
    const float* Wl = (l == 0) ? W1l : (l == 1) ? W2l : W3l;
    const float* Wr = (l == 0) ? W1r : (l == 1) ? W2r : W3r;
    float v = (k < 128) ? __ldg(Wl + r * 128 + k) : __ldg(Wr + r * 128 + k - 128);
    bf16 h = __float2bfloat16(v);
    whi[id] = h;
    wlo[id] = __float2bfloat16(v - __bfloat162float(h));
}

// ---------------- CSR build ----------------
__global__ void __launch_bounds__(256) zero_deg_kernel(int* __restrict__ deg)
{
    int i = blockIdx.x * blockDim.x + threadIdx.x;
    if (i < N_NODES) deg[i] = 0;
}
__global__ void __launch_bounds__(256) hist_kernel(
    const int* __restrict__ ei, int* __restrict__ deg)
{
    int e = blockIdx.x * blockDim.x + threadIdx.x;
    if (e >= N_EDGES) return;
    atomicAdd(deg + __ldg(ei + N_EDGES + e), 1);
}
__global__ void __launch_bounds__(1024) scan_kernel(
    const int* __restrict__ deg, int* __restrict__ off, int* __restrict__ cur)
{
    __shared__ int part[1024];
    const int tid = threadIdx.x;
    const int CH = (N_NODES + 1023) / 1024;
    const int start = tid * CH;
    int sum = 0;
    for (int i = 0; i < CH; ++i) {
        int idx = start + i;
        if (idx < N_NODES) sum += deg[idx];
    }
    part[tid] = sum;
    __syncthreads();
    for (int d = 1; d < 1024; d <<= 1) {
        int v = (tid >= d) ? part[tid - d] : 0;
        __syncthreads();
        part[tid] += v;
        __syncthreads();
    }
    int run = tid ? part[tid - 1] : 0;
    for (int i = 0; i < CH; ++i) {
        int idx = start + i;
        if (idx <= N_NODES) {
            off[idx] = run;
            if (idx < N_NODES) cur[idx] = run;
        }
        if (idx < N_NODES) run += deg[idx];
    }
}
__global__ void __launch_bounds__(256) fill_kernel(
    const int* __restrict__ ei, int* __restrict__ cur, int* __restrict__ srcs)
{
    int e = blockIdx.x * blockDim.x + threadIdx.x;
    if (e >= N_EDGES) return;
    int src = __ldg(ei + e);
    int dst = __ldg(ei + N_EDGES + e);
    int pos = atomicAdd(cur + dst, 1);
    srcs[pos] = src;
}

// ---------------- gather aggregation (bf16 hi/lo in, bf16 hi/lo out) ----------------
__global__ void __launch_bounds__(256) aggregate_kernel(
    const bf16* __restrict__ hHi,
    const bf16* __restrict__ hLo,
    const int*  __restrict__ off,
    const int*  __restrict__ srcs,
    bf16*       __restrict__ aHi,
    bf16*       __restrict__ aLo)
{
    int node = (blockIdx.x * blockDim.x + threadIdx.x) >> 5;
    int lane = threadIdx.x & 31;
    if (node >= N_NODES) return;
    int b = __ldg(off + node);
    int e = __ldg(off + node + 1);
    const int c0 = lane * 4;
    float4 acc = make_float4(0.f, 0.f, 0.f, 0.f);
    int i = b;
    for (; i + 3 < e; i += 4) {
        int s0 = __ldg(srcs + i + 0);
        int s1 = __ldg(srcs + i + 1);
        int s2 = __ldg(srcs + i + 2);
        int s3 = __ldg(srcs + i + 3);
        uint2 h0 = __ldg(reinterpret_cast<const uint2*>(hHi + (size_t)s0 * 128 + c0));
        uint2 l0 = __ldg(reinterpret_cast<const uint2*>(hLo + (size_t)s0 * 128 + c0));
        uint2 h1 = __ldg(reinterpret_cast<const uint2*>(hHi + (size_t)s1 * 128 + c0));
        uint2 l1 = __ldg(reinterpret_cast<const uint2*>(hLo + (size_t)s1 * 128 + c0));
        uint2 h2 = __ldg(reinterpret_cast<const uint2*>(hHi + (size_t)s2 * 128 + c0));
        uint2 l2 = __ldg(reinterpret_cast<const uint2*>(hLo + (size_t)s2 * 128 + c0));
        uint2 h3 = __ldg(reinterpret_cast<const uint2*>(hHi + (size_t)s3 * 128 + c0));
        uint2 l3 = __ldg(reinterpret_cast<const uint2*>(hLo + (size_t)s3 * 128 + c0));
        float4 v0 = rec4(h0, l0), v1 = rec4(h1, l1), v2 = rec4(h2, l2), v3 = rec4(h3, l3);
        acc.x += (v0.x + v1.x) + (v2.x + v3.x);
        acc.y += (v0.y + v1.y) + (v2.y + v3.y);
        acc.z += (v0.z + v1.z) + (v2.z + v3.z);
        acc.w += (v0.w + v1.w) + (v2.w + v3.w);
    }
    for (; i < e; ++i) {
        int s = __ldg(srcs + i);
        uint2 h0 = __ldg(reinterpret_cast<const uint2*>(hHi + (size_t)s * 128 + c0));
        uint2 l0 = __ldg(reinterpret_cast<const uint2*>(hLo + (size_t)s * 128 + c0));
        float4 v = rec4(h0, l0);
        acc.x += v.x; acc.y += v.y; acc.z += v.z; acc.w += v.w;
    }
    uint2 hi, lo;
    split4(acc, hi, lo);
    *reinterpret_cast<uint2*>(aHi + (size_t)node * 128 + c0) = hi;
    *reinterpret_cast<uint2*>(aLo + (size_t)node * 128 + c0) = lo;
}

// ================ WMMA bf16x2 SAGE GEMM, cp.async pipelined ================
// CTA tile 256x128, 8 warps in 4(m) x 2(n), warp tile 64x64.
// K = 256 in 4 chunks of 64: [agg 0-63][agg 64-127][h 0-63][h 64-127]
// SMEM stage: Ahi 256x72 | Alo 256x72 | Bhi 128x72 | Blo 128x72 (bf16), x2 stages.
#define LDT 72
#define A_HI_OFF 0
#define A_LO_OFF 36864
#define B_HI_OFF 73728
#define B_LO_OFF 92160
#define STAGE_BYTES 110592
#define SM_TOTAL (2 * STAGE_BYTES)   // 221184

__device__ __forceinline__ void load_chunk(
    int c, uint32_t stg, char* smem_stage,
    const bf16* aHi, const bf16* aLo,
    const bf16* hHi, const bf16* hLo,
    const bf16* wHi, const bf16* wLo,
    int block_row, int tid)
{
    const bf16* Ah = (c < 2) ? aHi : hHi;
    const bf16* Al = (c < 2) ? aLo : hLo;
    const int k0 = (c & 1) * 64;
    const bf16* srcH = Ah + (size_t)(block_row + tid) * 128 + k0;
    const bf16* srcL = Al + (size_t)(block_row + tid) * 128 + k0;
    uint32_t dH = stg + A_HI_OFF + tid * (LDT * 2);
    uint32_t dL = stg + A_LO_OFF + tid * (LDT * 2);
#pragma unroll
    for (int i = 0; i < 8; ++i) {
        cp16(dH + i * 16, srcH + i * 8);
        cp16(dL + i * 16, srcL + i * 8);
    }
    if (tid < 128) {
        const bf16* srcB = wHi + (size_t)tid * 256 + c * 64;
        uint32_t dB = stg + B_HI_OFF + tid * (LDT * 2);
#pragma unroll
        for (int i = 0; i < 8; ++i) cp16(dB + i * 16, srcB + i * 8);
    } else {
        const int r = tid - 128;
        const bf16* srcB = wLo + (size_t)r * 256 + c * 64;
        uint32_t dB = stg + B_LO_OFF + r * (LDT * 2);
#pragma unroll
        for (int i = 0; i < 8; ++i) cp16(dB + i * 16, srcB + i * 8);
    }
}

__global__ void __launch_bounds__(256)
sage_wmma_kernel(
    const bf16* __restrict__ aHi, const bf16* __restrict__ aLo,
    const bf16* __restrict__ hHi, const bf16* __restrict__ hLo,
    const bf16* __restrict__ wHi, const bf16* __restrict__ wLo,
    const float* __restrict__ bias,
    bf16* __restrict__ oHi, bf16* __restrict__ oLo,
    int do_relu)
{
    extern __shared__ char smem[];
    const uint32_t sbase = smem_u32(smem);
    const int tid = threadIdx.x;
    const int wid = tid >> 5;
    const int lane = tid & 31;
    const int block_row = blockIdx.x * 256;

    const int wm = (wid & 3) * 64;   // 4 m-tiles
    const int wn = (wid >> 2) * 64;  // 2 n-tiles

    wmma::fragment<wmma::accumulator, 16, 16, 16, float> acc[4][4];
#pragma unroll
    for (int i = 0; i < 4; ++i)
#pragma unroll
        for (int j = 0; j < 4; ++j) wmma::fill_fragment(acc[i][j], 0.f);

    // prime pipeline: chunks 0,1
    load_chunk(0, sbase, smem, aHi, aLo, hHi, hLo, wHi, wLo, block_row, tid);
    CP_COMMIT();
    load_chunk(1, sbase + STAGE_BYTES, smem, aHi, aLo, hHi, hLo, wHi, wLo, block_row, tid);
    CP_COMMIT();

#pragma unroll 1
    for (int c = 0; c < 4; ++c) {
        if (c < 3) CP_WAIT1(); else CP_WAIT0();
        __syncthreads();

        char* st = smem + (c & 1) * STAGE_BYTES;
        const bf16* sAhi = reinterpret_cast<const bf16*>(st + A_HI_OFF);
        const bf16* sAlo = reinterpret_cast<const bf16*>(st + A_LO_OFF);
        const bf16* sBhi = reinterpret_cast<const bf16*>(st + B_HI_OFF);
        const bf16* sBlo = reinterpret_cast<const bf16*>(st + B_LO_OFF);

#pragma unroll
        for (int ks = 0; ks < 4; ++ks) {
            wmma::fragment<wmma::matrix_a, 16, 16, 16, bf16, wmma::row_major> fah[4], fal[4];
#pragma unroll
            for (int i = 0; i < 4; ++i) {
                wmma::load_matrix_sync(fah[i], sAhi + (wm + i * 16) * LDT + ks * 16, LDT);
                wmma::load_matrix_sync(fal[i], sAlo + (wm + i * 16) * LDT + ks * 16, LDT);
            }
#pragma unroll
            for (int j = 0; j < 4; ++j) {
                wmma::fragment<wmma::matrix_b, 16, 16, 16, bf16, wmma::col_major> fbh, fbl;
                wmma::load_matrix_sync(fbh, sBhi + (wn + j * 16) * LDT + ks * 16, LDT);
                wmma::load_matrix_sync(fbl, sBlo + (wn + j * 16) * LDT + ks * 16, LDT);
#pragma unroll
                for (int i = 0; i < 4; ++i) {
                    wmma::mma_sync(acc[i][j], fah[i], fbh, acc[i][j]);
                    wmma::mma_sync(acc[i][j], fah[i], fbl, acc[i][j]);
                    wmma::mma_sync(acc[i][j], fal[i], fbh, acc[i][j]);
                }
            }
        }
        __syncthreads();
        if (c + 2 < 4) {
            load_chunk(c + 2, sbase + (c & 1) * STAGE_BYTES, smem,
                       aHi, aLo, hHi, hLo, wHi, wLo, block_row, tid);
            CP_COMMIT();
        }
    }

    // ---- epilogue: per-warp 64x64 f32 staging in (reused) SMEM ----
    __syncthreads();
    float* sEpi = reinterpret_cast<float*>(smem) + wid * 64 * 64;
#pragma unroll
    for (int i = 0; i < 4; ++i)
#pragma unroll
        for (int j = 0; j < 4; ++j)
            wmma::store_matrix_sync(sEpi + (i * 16) * 64 + j * 16, acc[i][j], 64,
                                    wmma::mem_row_major);
    __syncwarp();

#pragma unroll
    for (int rr = 0; rr < 2; ++rr) {
        const int r = lane * 2 + rr;
        const size_t grow = (size_t)(block_row + wm + r);
#pragma unroll
        for (int cb = 0; cb < 64; cb += 4) {
            float4 v = *reinterpret_cast<float4*>(sEpi + r * 64 + cb);
            v.x += __ldg(bias + wn + cb + 0);
            v.y += __ldg(bias + wn + cb + 1);
            v.z += __ldg(bias + wn + cb + 2);
            v.w += __ldg(bias + wn + cb + 3);
            if (do_relu) {
                v.x = fmaxf(v.x, 0.f); v.y = fmaxf(v.y, 0.f);
                v.z = fmaxf(v.z, 0.f); v.w = fmaxf(v.w, 0.f);
            }
            uint2 hi, lo;
            split4(v, hi, lo);
            *reinterpret_cast<uint2*>(oHi + grow * 128 + wn + cb) = hi;
            *reinterpret_cast<uint2*>(oLo + grow * 128 + wn + cb) = lo;
        }
    }
}

// ---------------- pooling (bf16 hi/lo in) ----------------
__global__ void __launch_bounds__(256) pool_kernel(
    const bf16* __restrict__ hHi,
    const bf16* __restrict__ hLo,
    const int*  __restrict__ batch,
    float*      __restrict__ pooled)
{
    int node = (blockIdx.x * blockDim.x + threadIdx.x) >> 5;
    int lane = threadIdx.x & 31;
    if (node >= N_NODES) return;
    int g = __ldg(batch + node);
    uint2 h = __ldg(reinterpret_cast<const uint2*>(hHi + (size_t)node * 128 + lane * 4));
    uint2 l = __ldg(reinterpret_cast<const uint2*>(hLo + (size_t)node * 128 + lane * 4));
    float4 v = rec4(h, l);
    float* ap = pooled + (size_t)g * HIDDEN + lane * 4;
    asm volatile("red.global.add.v4.f32 [%0], {%1,%2,%3,%4};"
                 :: "l"(ap), "f"(v.x), "f"(v.y), "f"(v.z), "f"(v.w) : "memory");
}

// ---------------- output head ----------------
__global__ void out_kernel(
    const float* __restrict__ pooled,
    const float* __restrict__ Wout,
    const float* __restrict__ bout,
    float*       __restrict__ out)
{
    int idx = blockIdx.x * blockDim.x + threadIdx.x;
    if (idx >= NUM_GRAPHS * N_CLASSES) return;
    int g = idx / N_CLASSES;
    int c = idx % N_CLASSES;
    float s = __ldg(bout + c);
    const float* p = pooled + (size_t)g * HIDDEN;
    const float* w = Wout + (size_t)c * HIDDEN;
#pragma unroll 8
    for (int k = 0; k < HIDDEN; ++k) s = fmaf(p[k], w[k], s);
    out[idx] = s;
}

// ---------------- launch ----------------
extern "C" void kernel_launch(void* const* d_in, const int* in_sizes, int n_in,
                              void* d_out, int out_size)
{
    const float* x     = (const float*)d_in[0];
    const int*   ei    = (const int*)  d_in[1];
    const int*   batch = (const int*)  d_in[2];
    const float* W1l = (const float*)d_in[3];
    const float* b1  = (const float*)d_in[4];
    const float* W1r = (const float*)d_in[5];
    const float* W2l = (const float*)d_in[6];
    const float* b2  = (const float*)d_in[7];
    const float* W2r = (const float*)d_in[8];
    const float* W3l = (const float*)d_in[9];
    const float* b3  = (const float*)d_in[10];
    const float* W3r = (const float*)d_in[11];
    const float* Wout = (const float*)d_in[12];
    const float* bout = (const float*)d_in[13];
    float* out = (float*)d_out;

    bf16 *xhi, *xlo, *ahi, *alo, *h0hi, *h0lo, *h1hi, *h1lo, *whi, *wlo;
    float *pooled;
    int *deg, *off, *cur, *srcs;
    cudaGetSymbolAddress((void**)&xhi,  g_xhi);
    cudaGetSymbolAddress((void**)&xlo,  g_xlo);
    cudaGetSymbolAddress((void**)&ahi,  g_ahi);
    cudaGetSymbolAddress((void**)&alo,  g_alo);
    cudaGetSymbolAddress((void**)&h0hi, g_h0hi);
    cudaGetSymbolAddress((void**)&h0lo, g_h0lo);
    cudaGetSymbolAddress((void**)&h1hi, g_h1hi);
    cudaGetSymbolAddress((void**)&h1lo, g_h1lo);
    cudaGetSymbolAddress((void**)&whi,  g_whi);
    cudaGetSymbolAddress((void**)&wlo,  g_wlo);
    cudaGetSymbolAddress((void**)&pooled, g_pooled);
    cudaGetSymbolAddress((void**)&deg,  g_deg);
    cudaGetSymbolAddress((void**)&off,  g_off);
    cudaGetSymbolAddress((void**)&cur,  g_cur);
    cudaGetSymbolAddress((void**)&srcs, g_srcs);

    cudaFuncSetAttribute(sage_wmma_kernel,
                         cudaFuncAttributeMaxDynamicSharedMemorySize, SM_TOTAL);

    const int edge_blocks = (N_EDGES + 255) / 256;
    const int node_blocks = (N_NODES + 255) / 256;
    const int gemm_blocks = N_PAD / 256;   // 391
    const int warp_blocks = (N_NODES * 32 + 255) / 256;

    // conversions
    cvt_x_kernel<<<(N_NODES * 32 + 255) / 256, 256>>>(x, xhi, xlo);
    cvt_w_kernel<<<(3 * 128 * 256 + 255) / 256, 256>>>(W1l, W1r, W2l, W2r, W3l, W3r, whi, wlo);

    // CSR build
    zero_deg_kernel<<<node_blocks, 256>>>(deg);
    hist_kernel<<<edge_blocks, 256>>>(ei, deg);
    scan_kernel<<<1, 1024>>>(deg, off, cur);
    fill_kernel<<<edge_blocks, 256>>>(ei, cur, srcs);

    // layer 1: x -> h0
    aggregate_kernel<<<warp_blocks, 256>>>(xhi, xlo, off, srcs, ahi, alo);
    sage_wmma_kernel<<<gemm_blocks, 256, SM_TOTAL>>>(ahi, alo, xhi, xlo,
        whi, wlo, b1, h0hi, h0lo, 1);

    // layer 2: h0 -> h1
    aggregate_kernel<<<warp_blocks, 256>>>(h0hi, h0lo, off, srcs, ahi, alo);
    sage_wmma_kernel<<<gemm_blocks, 256, SM_TOTAL>>>(ahi, alo, h0hi, h0lo,
        whi + 32768, wlo + 32768, b2, h1hi, h1lo, 1);

    // layer 3: h1 -> h0 (reuse, no relu)
    aggregate_kernel<<<warp_blocks, 256>>>(h1hi, h1lo, off, srcs, ahi, alo);
    sage_wmma_kernel<<<gemm_blocks, 256, SM_TOTAL>>>(ahi, alo, h1hi, h1lo,
        whi + 65536, wlo + 65536, b3, h0hi, h0lo, 0);

    // pool + head
    cudaMemsetAsync(pooled, 0, NUM_GRAPHS * HIDDEN * sizeof(float));
    pool_kernel<<<warp_blocks, 256>>>(h0hi, h0lo, batch, pooled);
    out_kernel<<<(NUM_GRAPHS * N_CLASSES + 127) / 128, 128>>>(pooled, Wout, bout, out);
}